// round 16
// baseline (speedup 1.0000x reference)
#include <cuda_runtime.h>

#define FULLMASK 0xffffffffu

__device__ __forceinline__ float ftanh(float x) {
    float y;
    asm("tanh.approx.f32 %0, %1;" : "=f"(y) : "f"(x));
    return y;
}
__device__ __forceinline__ float frcp(float x) {
    float y;
    asm("rcp.approx.f32 %0, %1;" : "=f"(y) : "f"(x));
    return y;
}
__device__ __forceinline__ float softplusf(float x) {
    return log1pf(__expf(x));
}

// TWO warps per batch element (64 threads). Serial algebra duplicated per warp
// (no sync); parallel bulk split across warps. 2x2 block-pivot dual-LDL chol,
// cofactor 4x4 inverse.
__global__ void __launch_bounds__(64) ukf_kernel(
    const float* __restrict__ X0, const float* __restrict__ u, const float* __restrict__ yy,
    const float* __restrict__ W1, const float* __restrict__ b1,
    const float* __restrict__ W2, const float* __restrict__ b2,
    const float* __restrict__ Hm, const float* __restrict__ lq,
    const float* __restrict__ lr, const float* __restrict__ lp0,
    float* __restrict__ outX, float* __restrict__ outP,
    float* __restrict__ outQ, float* __restrict__ outR,
    int T)
{
    const float JIT = 1e-4f;
    const int b = blockIdx.x;
    const int tid = threadIdx.x;
    const int lane = tid & 31;
    const int wid = tid >> 5;

    __shared__ __align__(16) float sP[64];         // P_new
    __shared__ __align__(16) float sPp[64];        // P_pred
    __shared__ __align__(16) float sHid[17 * 36];  // tanh activations
    __shared__ __align__(16) float sDxT[8 * 20];   // dx transposed [state][s]
    __shared__ __align__(16) float sX[8];
    __shared__ __align__(16) float sXp[8];
    __shared__ float sXs[16];                      // x_pred partials (2 warps x 8)

    const int o  = lane & 7;    // state/output index (same pattern both warps)
    const int m  = lane & 3;    // measurement index
    const int pn = lane >> 2;   // Pxy row
    const int si = pn & 3;      // Sy row
    const int g8 = lane & 8;    // dual-chol group
    const int b4 = lane & 28;
    const int sg = tid >> 3;    // sigma base (0..7) for output layer
    const int ci = tid >> 3;    // Cx/P_new entry row
    const int cj = tid & 7;     // Cx/P_new entry col

    // ---- per-lane weights (identical in both warps) ----
    float w1c[10];
    #pragma unroll
    for (int d = 0; d < 10; ++d) w1c[d] = W1[d * 32 + lane];
    float b1v = b1[lane];
    float w2c[32];
    #pragma unroll
    for (int h = 0; h < 32; ++h) w2c[h] = W2[h * 8 + o];
    float b2o = b2[o];
    float hmr[8];
    #pragma unroll
    for (int d = 0; d < 8; ++d) hmr[d] = Hm[m * 8 + d];
    float hsr[8];
    #pragma unroll
    for (int d = 0; d < 8; ++d) hsr[d] = Hm[si * 8 + d];

    const float radd = (si == m) ? softplusf(lr[si]) : 0.0f;
    const float corrP = (softplusf(lq[pn]) + JIT) * Hm[m * 8 + pn];
    const float cDt = (ci == cj) ? (softplusf(lq[ci]) + JIT) : 0.0f;  // Cx diag add

    // ---- init ----
    float xreg = X0[b * 8 + o];
    if (tid < 8) { sX[tid] = xreg; outX[(long)b * T * 8 + tid] = xreg; }
    {
        int ii = tid >> 3, jj = tid & 7;
        float pv = (ii == jj) ? softplusf(lp0[ii]) : 0.0f;
        sP[tid] = pv;
        sPp[tid] = (ii == jj) ? 1.0f : 0.0f;
        outP[(long)b * T * 64 + tid] = pv;
    }
    if (tid == 0) { outQ[(long)b * T] = 0.0f; outR[(long)b * T] = 0.0f; }
    __syncthreads();

    for (int t = 1; t < T; ++t) {
        const float2 uv = *reinterpret_cast<const float2*>(&u[((long)b * T + (t - 1)) * 2]);
        const float yraw = yy[((long)b * T + t) * 4 + m];

        // ---- hidden-layer base (redundant per warp) ----
        float bx;
        {
            const float4* xp4 = reinterpret_cast<const float4*>(sX);
            float4 x0 = xp4[0], x1 = xp4[1];
            float ba = b1v + uv.x * w1c[8] + x0.x * w1c[0] + x0.y * w1c[1] + x0.z * w1c[2];
            float bb = uv.y * w1c[9] + x0.w * w1c[3] + x1.x * w1c[4] + x1.y * w1c[5];
            bx = ba + bb + x1.z * w1c[6] + x1.w * w1c[7];
        }

        // ==== dual 2x2 block-pivot LDL (redundant per warp): g8=0 -> A, g8=8 -> Pp_prev ====
        float a[8];
        {
            const float4* srcp = reinterpret_cast<const float4*>(g8 ? &sPp[o * 8] : &sP[o * 8]);
            float4 r0 = srcp[0], r1 = srcp[1];
            a[0] = r0.x; a[1] = r0.y; a[2] = r0.z; a[3] = r0.w;
            a[4] = r1.x; a[5] = r1.y; a[6] = r1.z; a[7] = r1.w;
            if (!g8) {
                #pragma unroll
                for (int c = 0; c < 8; ++c)
                    a[c] = 8.0f * a[c] + ((c == o) ? JIT : 0.0f);
            }
        }
        float detp = 1.0f;
        #pragma unroll
        for (int k = 0; k < 8; k += 2) {
            float d00 = __shfl_sync(FULLMASK, a[k],     g8 + k);
            float d01 = __shfl_sync(FULLMASK, a[k],     g8 + k + 1);
            float d11 = __shfl_sync(FULLMASK, a[k + 1], g8 + k + 1);
            float det = d00 * d11 - d01 * d01;
            detp *= det;
            float rdet = frcp(det);
            float i00 =  d11 * rdet;
            float i01 = -d01 * rdet;
            float i11 =  d00 * rdet;
            float t0 = a[k] * i00 + a[k + 1] * i01;
            float t1 = a[k] * i01 + a[k + 1] * i11;
            #pragma unroll
            for (int jj = k + 2; jj < 8; ++jj) {
                float ljA = __shfl_sync(FULLMASK, a[k],     g8 + jj);
                float ljB = __shfl_sync(FULLMASK, a[k + 1], g8 + jj);
                a[jj] -= t0 * ljA + t1 * ljB;
            }
            float inv0 = rsqrtf(d00);
            float c00 = d00 * inv0;
            float c10 = d01 * inv0;
            float c11s = d11 - c10 * c10;
            float inv1 = rsqrtf(c11s);
            float c11 = c11s * inv1;
            float nk  = (o == k) ? c00 : ((o == k + 1) ? c10 : t0 * c00 + t1 * c10);
            float nk1 = (o == k) ? 0.0f : ((o == k + 1) ? c11 : t1 * c11);
            a[k] = nk;
            a[k + 1] = nk1;
        }
        if (tid == 8 && t >= 2)    // warp 0, lane 8 (Pp group)
            outQ[(long)b * T + (t - 1)] = 0.5f * __logf(detp);

        // true L row o (A group lives in lanes 0-7)
        float Lrow[8];
        #pragma unroll
        for (int i = 0; i < 8; ++i) {
            float lv = __shfl_sync(FULLMASK, a[i], o);
            Lrow[i] = (i <= o) ? lv : 0.0f;
        }
        // G[i] = sum_{d>=i} L[d][i]*w1c[d]
        float G[8];
        #pragma unroll
        for (int i = 0; i < 8; ++i) {
            float g = 0.0f;
            #pragma unroll
            for (int d = i; d < 8; ++d)
                g += __shfl_sync(FULLMASK, a[i], d) * w1c[d];
            G[i] = g;
        }

        // ---- tanh split: warp 0 -> s=0..8 ; warp 1 -> s=9..16 ----
        if (wid == 0) {
            sHid[0 * 36 + lane] = ftanh(bx);
            #pragma unroll
            for (int i = 0; i < 8; ++i)
                sHid[(1 + i) * 36 + lane] = ftanh(bx + G[i]);
        } else {
            #pragma unroll
            for (int i = 0; i < 8; ++i)
                sHid[(9 + i) * 36 + lane] = ftanh(bx - G[i]);
        }
        __syncthreads();

        // ==== output layer: 3 groups, s = sg + 8g ====
        float pf[3];
        float xsum = 0.0f;
        #pragma unroll
        for (int g = 0; g < 3; ++g) {
            int s = sg + 8 * g;
            bool valid = (s < 17);
            int ss = valid ? s : 0;
            const float4* hp = reinterpret_cast<const float4*>(&sHid[ss * 36]);
            float ea = 0.0f, eb = 0.0f;
            #pragma unroll
            for (int hh = 0; hh < 8; ++hh) {
                float4 hv = hp[hh];
                ea += hv.x * w2c[4 * hh] + hv.y * w2c[4 * hh + 1];
                eb += hv.z * w2c[4 * hh + 2] + hv.w * w2c[4 * hh + 3];
            }
            float e = b2o + ea + eb;
            float delta = 0.0f;
            if (ss >= 1 && ss <= 8) delta = Lrow[ss - 1];
            else if (ss >= 9)       delta = -Lrow[ss - 9];
            float p = xreg + delta + e;
            pf[g] = p;
            if (valid && s >= 1) xsum += p;
        }
        // warp-local partial (over this warp's 4 sg groups), then cross-warp via smem
        xsum += __shfl_xor_sync(FULLMASK, xsum, 8);
        xsum += __shfl_xor_sync(FULLMASK, xsum, 16);
        if (lane < 8) sXs[wid * 8 + lane] = xsum;
        __syncthreads();
        const float xpred = (sXs[o] + sXs[8 + o]) * 0.0625f;
        if (tid < 8) sXp[tid] = xpred;
        #pragma unroll
        for (int g = 0; g < 3; ++g) {
            int s = sg + 8 * g;
            if (s < 17) sDxT[o * 20 + s] = pf[g] - xpred;
        }
        __syncthreads();

        // ==== Cx: one entry (ci,cj) per thread ====
        float ppv;
        {
            const float4* ri = reinterpret_cast<const float4*>(&sDxT[ci * 20]);
            const float4* rj = reinterpret_cast<const float4*>(&sDxT[cj * 20]);
            float4 xi = ri[0], xj = rj[0];
            float da = 32.0f * xi.x * xj.x + xi.y * xj.y;   // Wc0 = 2 = 32/16
            float db = xi.z * xj.z + xi.w * xj.w;
            #pragma unroll
            for (int c = 1; c < 4; ++c) {
                xi = ri[c]; xj = rj[c];
                da += xi.x * xj.x + xi.y * xj.y;
                db += xi.z * xj.z + xi.w * xj.w;
            }
            float dot = da + db + sDxT[ci * 20 + 16] * sDxT[cj * 20 + 16];
            ppv = dot * 0.0625f + cDt;
            sPp[ci * 8 + cj] = ppv;
        }
        __syncthreads();

        // ==== Pxy / Sy / inverse / K (redundant per warp) ====
        float pxy;
        {
            const float4* pr = reinterpret_cast<const float4*>(&sPp[pn * 8]);
            float4 p0 = pr[0], p1v = pr[1];
            float pa = p0.x * hmr[0] + p0.y * hmr[1] + p0.z * hmr[2];
            float pb = p0.w * hmr[3] + p1v.x * hmr[4] + p1v.y * hmr[5];
            float pc = p1v.z * hmr[6] + p1v.w * hmr[7] - corrP;
            pxy = pa + pb + pc;
        }
        float syv;
        {
            float sa = radd, sb = 0.0f;
            #pragma unroll
            for (int d = 0; d < 8; d += 2) {
                sa += hsr[d] * __shfl_sync(FULLMASK, pxy, d * 4 + m);
                sb += hsr[d + 1] * __shfl_sync(FULLMASK, pxy, (d + 1) * 4 + m);
            }
            syv = sa + sb;
        }
        const float Saa = __shfl_sync(FULLMASK, syv, 0);
        const float Sab = __shfl_sync(FULLMASK, syv, 1);
        const float Sac = __shfl_sync(FULLMASK, syv, 2);
        const float Sad = __shfl_sync(FULLMASK, syv, 3);
        const float Sbb = __shfl_sync(FULLMASK, syv, 5);
        const float Sbc = __shfl_sync(FULLMASK, syv, 6);
        const float Sbd = __shfl_sync(FULLMASK, syv, 7);
        const float Scc = __shfl_sync(FULLMASK, syv, 10);
        const float Scd = __shfl_sync(FULLMASK, syv, 11);
        const float Sdd = __shfl_sync(FULLMASK, syv, 15);

        const float s0 = Saa * Sbb - Sab * Sab;
        const float s1 = Saa * Sbc - Sab * Sac;
        const float s2 = Saa * Sbd - Sab * Sad;
        const float s3 = Sab * Sbc - Sbb * Sac;
        const float s4 = Sab * Sbd - Sbb * Sad;
        const float s5 = Sac * Sbd - Sbc * Sad;
        const float c5 = Scc * Sdd - Scd * Scd;
        const float c4 = Sbc * Sdd - Sbd * Scd;
        const float c3 = Sbc * Scd - Sbd * Scc;
        const float c2 = Sac * Sdd - Sad * Scd;
        const float c1 = Sac * Scd - Sad * Scc;
        const float det = s0 * c5 - s1 * c4 + s2 * c3 + s3 * c2 - s4 * c1 + s5 * s5;
        const float rdet = __fdividef(1.0f, det);
        if (tid == 0) outR[(long)b * T + t] = 0.5f * __logf(det);
        const float A00 =  Sbb * c5 - Sbc * c4 + Sbd * c3;
        const float A01 = -Sab * c5 + Sac * c4 - Sad * c3;
        const float A02 =  Sbd * s5 - Scd * s4 + Sdd * s3;
        const float A03 = -Sbc * s5 + Scc * s4 - Scd * s3;
        const float A11 =  Saa * c5 - Sac * c2 + Sad * c1;
        const float A12 = -Sad * s5 + Scd * s2 - Sdd * s1;
        const float A13 =  Sac * s5 - Scc * s2 + Scd * s1;
        const float A22 =  Sad * s4 - Sbd * s2 + Sdd * s0;
        const float A23 = -Sac * s4 + Sbc * s2 - Scd * s0;
        const float A33 =  Sac * s3 - Sbc * s1 + Scc * s0;

        const float w0 = __shfl_sync(FULLMASK, pxy, o * 4 + 0);
        const float w1 = __shfl_sync(FULLMASK, pxy, o * 4 + 1);
        const float w2 = __shfl_sync(FULLMASK, pxy, o * 4 + 2);
        const float w3 = __shfl_sync(FULLMASK, pxy, o * 4 + 3);
        const float z0 = (w0 * A00 + w1 * A01 + w2 * A02 + w3 * A03) * rdet;
        const float z1 = (w0 * A01 + w1 * A11 + w2 * A12 + w3 * A13) * rdet;
        const float z2 = (w0 * A02 + w1 * A12 + w2 * A22 + w3 * A23) * rdet;
        const float z3 = (w0 * A03 + w1 * A13 + w2 * A23 + w3 * A33) * rdet;

        // ==== innovation & state update (redundant; warp 0 writes) ====
        float inno;
        {
            const float4* xp4 = reinterpret_cast<const float4*>(sXp);
            float4 x0 = xp4[0], x1 = xp4[1];
            float ya = hmr[0] * x0.x + hmr[1] * x0.y + hmr[2] * x0.z + hmr[3] * x0.w;
            float yb = hmr[4] * x1.x + hmr[5] * x1.y + hmr[6] * x1.z + hmr[7] * x1.w;
            inno = yraw - (ya + yb);
        }
        const float in0 = __shfl_sync(FULLMASK, inno, b4 + 0);
        const float in1 = __shfl_sync(FULLMASK, inno, b4 + 1);
        const float in2 = __shfl_sync(FULLMASK, inno, b4 + 2);
        const float in3 = __shfl_sync(FULLMASK, inno, b4 + 3);
        float xn = xpred + z0 * in0 + z1 * in1 + z2 * in2 + z3 * in3;
        xreg = xn;
        if (tid < 8) { sX[tid] = xn; outX[((long)b * T + t) * 8 + tid] = xn; }

        // ==== P_new: one entry (ci,cj) per thread ====
        {
            const float Ki0 = __shfl_sync(FULLMASK, z0, ci);
            const float Ki1 = __shfl_sync(FULLMASK, z1, ci);
            const float Ki2 = __shfl_sync(FULLMASK, z2, ci);
            const float Ki3 = __shfl_sync(FULLMASK, z3, ci);
            const float Wj0 = __shfl_sync(FULLMASK, w0, cj);
            const float Wj1 = __shfl_sync(FULLMASK, w1, cj);
            const float Wj2 = __shfl_sync(FULLMASK, w2, cj);
            const float Wj3 = __shfl_sync(FULLMASK, w3, cj);
            float p = ppv - (Ki0 * Wj0 + Ki1 * Wj1 + Ki2 * Wj2 + Ki3 * Wj3)
                    + ((ci == cj) ? JIT : 0.0f);
            sP[ci * 8 + cj] = p;
            outP[((long)b * T + t) * 64 + ci * 8 + cj] = p;
        }
        __syncthreads();
    }

    // ==== epilogue: q_e[T-1] (warp 0 only, scalar root-free pivots) ====
    if (wid == 0) {
        float a[8];
        #pragma unroll
        for (int c = 0; c < 8; ++c) a[c] = sPp[o * 8 + c];
        float myd = 1.0f;
        #pragma unroll
        for (int k = 0; k < 8; ++k) {
            float dk = __shfl_sync(FULLMASK, a[k], k);
            float rc = frcp(dk);
            myd = (o == k) ? dk : myd;
            float tt = a[k] * rc;
            #pragma unroll
            for (int jj = k + 1; jj < 8; ++jj) {
                float lj = __shfl_sync(FULLMASK, a[k], jj);
                a[jj] -= tt * lj;
            }
        }
        float lg = __logf(myd);
        lg += __shfl_xor_sync(FULLMASK, lg, 1);
        lg += __shfl_xor_sync(FULLMASK, lg, 2);
        lg += __shfl_xor_sync(FULLMASK, lg, 4);
        if (lane == 0) outQ[(long)b * T + (T - 1)] = 0.5f * lg;
    }
}

extern "C" void kernel_launch(void* const* d_in, const int* in_sizes, int n_in,
                              void* d_out, int out_size) {
    const float* X0  = (const float*)d_in[0];
    const float* u   = (const float*)d_in[1];
    const float* yv  = (const float*)d_in[2];
    const float* W1  = (const float*)d_in[3];
    const float* b1  = (const float*)d_in[4];
    const float* W2  = (const float*)d_in[5];
    const float* b2  = (const float*)d_in[6];
    const float* Hm  = (const float*)d_in[7];
    const float* lq  = (const float*)d_in[8];
    const float* lr  = (const float*)d_in[9];
    const float* lp0 = (const float*)d_in[10];

    const int B = in_sizes[0] / 8;                 // 1024
    const int T = in_sizes[1] / (B * 2);           // 256

    float* out  = (float*)d_out;
    float* outX = out;
    float* outP = out + (long)B * T * 8;
    float* outQ = out + (long)B * T * (8 + 64);
    float* outR = outQ + (long)B * T;

    ukf_kernel<<<B, 64>>>(X0, u, yv, W1, b1, W2, b2, Hm, lq, lr, lp0,
                          outX, outP, outQ, outR, T);
}

// round 17
// speedup vs baseline: 1.9654x; 1.9654x over previous
#include <cuda_runtime.h>

#define FULLMASK 0xffffffffu

__device__ __forceinline__ float ftanh(float x) {
    float y;
    asm("tanh.approx.f32 %0, %1;" : "=f"(y) : "f"(x));
    return y;
}
__device__ __forceinline__ float frcp(float x) {
    float y;
    asm("rcp.approx.f32 %0, %1;" : "=f"(y) : "f"(x));
    return y;
}
__device__ __forceinline__ float softplusf(float x) {
    return log1pf(__expf(x));
}

// One warp per batch element. Warp-synchronous UKF.
// 8x8 dual factorization via 2x2 block-pivot LDL -> true Cholesky factor.
// 4x4 Sy solved by closed-form cofactor inverse.
__global__ void __launch_bounds__(32) ukf_kernel(
    const float* __restrict__ X0, const float* __restrict__ u, const float* __restrict__ yy,
    const float* __restrict__ W1, const float* __restrict__ b1,
    const float* __restrict__ W2, const float* __restrict__ b2,
    const float* __restrict__ Hm, const float* __restrict__ lq,
    const float* __restrict__ lr, const float* __restrict__ lp0,
    float* __restrict__ outX, float* __restrict__ outP,
    float* __restrict__ outQ, float* __restrict__ outR,
    int T)
{
    const float JIT = 1e-4f;
    const int b = blockIdx.x;
    const int lane = threadIdx.x;

    __shared__ __align__(16) float sP[64];         // P_new (8x8, stride 8)
    __shared__ __align__(16) float sPp[64];        // P_pred (8x8, stride 8)
    __shared__ __align__(16) float sHid[17 * 36];  // tanh activations
    __shared__ __align__(16) float sDxT[8 * 20];   // dx transposed [col][s]
    __shared__ __align__(16) float sX[8];          // current state
    __shared__ __align__(16) float sXp[8];         // x_pred

    const int o  = lane & 7;    // state index
    const int q  = lane >> 3;   // sigma group / P row base
    const int m  = lane & 3;    // measurement index
    const int pn = lane >> 2;   // Pxy row
    const int si = pn & 3;      // Sy row index
    const int i1 = q, i2 = q + 4;
    const int g8 = lane & 8;    // dual-chol shuffle base
    const int b4 = lane & 28;   // 4-group base

    // ---- persistent per-lane weights in registers ----
    float w1c[10];
    #pragma unroll
    for (int d = 0; d < 10; ++d) w1c[d] = W1[d * 32 + lane];
    float b1v = b1[lane];
    float w2c[32];
    #pragma unroll
    for (int h = 0; h < 32; ++h) w2c[h] = W2[h * 8 + o];
    float b2o = b2[o];
    float hmr[8];
    #pragma unroll
    for (int d = 0; d < 8; ++d) hmr[d] = Hm[m * 8 + d];
    float hsr[8];
    #pragma unroll
    for (int d = 0; d < 8; ++d) hsr[d] = Hm[si * 8 + d];

    const float cD1 = (i1 == o) ? (softplusf(lq[i1]) + JIT) : 0.0f;
    const float cD2 = (i2 == o) ? (softplusf(lq[i2]) + JIT) : 0.0f;
    const float radd = (si == m) ? softplusf(lr[si]) : 0.0f;
    const float corrP = (softplusf(lq[pn]) + JIT) * Hm[m * 8 + pn];  // Pxy diag fix

    // ---- init: t=0 outputs, P0, identity Pp ----
    float xreg = X0[b * 8 + o];
    if (lane < 8) { sX[lane] = xreg; outX[(long)b * T * 8 + lane] = xreg; }
    #pragma unroll
    for (int rep = 0; rep < 2; ++rep) {
        int idx = lane + 32 * rep;
        int ii = idx >> 3, jj = idx & 7;
        float pv = (ii == jj) ? softplusf(lp0[ii]) : 0.0f;
        sP[idx] = pv;
        sPp[idx] = (ii == jj) ? 1.0f : 0.0f;
        outP[(long)b * T * 64 + idx] = pv;
    }
    if (lane == 0) { outQ[(long)b * T] = 0.0f; outR[(long)b * T] = 0.0f; }
    __syncwarp();

    for (int t = 1; t < T; ++t) {
        // ---- early loads (off critical path) ----
        const float2 uv = *reinterpret_cast<const float2*>(&u[((long)b * T + (t - 1)) * 2]);
        const float yraw = yy[((long)b * T + t) * 4 + m];

        // ---- hidden-layer base from sX (2 LDS.128) ----
        float bx;
        {
            const float4* xp4 = reinterpret_cast<const float4*>(sX);
            float4 x0 = xp4[0], x1 = xp4[1];
            float ba = b1v + uv.x * w1c[8] + x0.x * w1c[0] + x0.y * w1c[1] + x0.z * w1c[2];
            float bb = uv.y * w1c[9] + x0.w * w1c[3] + x1.x * w1c[4] + x1.y * w1c[5];
            bx = ba + bb + x1.z * w1c[6] + x1.w * w1c[7];
        }

        // ==== dual 2x2 block-pivot LDL: bit3=0 -> A=8P+JIT*I ; bit3=1 -> Pp_prev ====
        float a[8];
        {
            const float4* srcp = reinterpret_cast<const float4*>(g8 ? &sPp[o * 8] : &sP[o * 8]);
            float4 r0 = srcp[0], r1 = srcp[1];
            a[0] = r0.x; a[1] = r0.y; a[2] = r0.z; a[3] = r0.w;
            a[4] = r1.x; a[5] = r1.y; a[6] = r1.z; a[7] = r1.w;
            if (!g8) {
                #pragma unroll
                for (int c = 0; c < 8; ++c)
                    a[c] = 8.0f * a[c] + ((c == o) ? JIT : 0.0f);
            }
        }
        float detp = 1.0f;   // product of 2x2 pivot-block determinants
        #pragma unroll
        for (int k = 0; k < 8; k += 2) {
            float d00 = __shfl_sync(FULLMASK, a[k],     g8 + k);
            float d01 = __shfl_sync(FULLMASK, a[k],     g8 + k + 1);  // row k+1, col k
            float d11 = __shfl_sync(FULLMASK, a[k + 1], g8 + k + 1);
            float det = d00 * d11 - d01 * d01;
            detp *= det;
            float rdet = frcp(det);
            float i00 =  d11 * rdet;
            float i01 = -d01 * rdet;
            float i11 =  d00 * rdet;
            float t0 = a[k] * i00 + a[k + 1] * i01;
            float t1 = a[k] * i01 + a[k + 1] * i11;
            #pragma unroll
            for (int jj = k + 2; jj < 8; ++jj) {
                float ljA = __shfl_sync(FULLMASK, a[k],     g8 + jj);
                float ljB = __shfl_sync(FULLMASK, a[k + 1], g8 + jj);
                a[jj] -= t0 * ljA + t1 * ljB;
            }
            // chol(D) (off the recurrence chain) and transform to TRUE L cols
            float inv0 = rsqrtf(d00);
            float c00 = d00 * inv0;
            float c10 = d01 * inv0;
            float c11s = d11 - c10 * c10;
            float inv1 = rsqrtf(c11s);
            float c11 = c11s * inv1;
            float nk  = (o == k) ? c00 : ((o == k + 1) ? c10 : t0 * c00 + t1 * c10);
            float nk1 = (o == k) ? 0.0f : ((o == k + 1) ? c11 : t1 * c11);
            a[k] = nk;
            a[k + 1] = nk1;
        }
        // deferred q_e of previous step (lanes 8-15 factored Pp_prev)
        if (lane == 8 && t >= 2)
            outQ[(long)b * T + (t - 1)] = 0.5f * __logf(detp);

        // true L row o (zeros above diagonal)
        float Lrow[8];
        #pragma unroll
        for (int i = 0; i < 8; ++i) {
            float lv = __shfl_sync(FULLMASK, a[i], o);
            Lrow[i] = (i <= o) ? lv : 0.0f;
        }
        // G[i] = sum_{d>=i} L[d][i]*w1c[d]  (true L in a[], lanes 0-7 = A group)
        float G[8];
        #pragma unroll
        for (int i = 0; i < 8; ++i) {
            float g = 0.0f;
            #pragma unroll
            for (int d = i; d < 8; ++d)
                g += __shfl_sync(FULLMASK, a[i], d) * w1c[d];
            G[i] = g;
        }

        sHid[0 * 36 + lane] = ftanh(bx);
        #pragma unroll
        for (int i = 0; i < 8; ++i) {
            sHid[(1 + i) * 36 + lane] = ftanh(bx + G[i]);
            sHid[(9 + i) * 36 + lane] = ftanh(bx - G[i]);
        }
        __syncwarp();

        // ==== output layer + x_pred + dx (stored transposed) ====
        float pf[5];
        float xsum = 0.0f;
        #pragma unroll
        for (int g = 0; g < 5; ++g) {
            int s = 4 * g + q;
            bool valid = (s < 17);
            int ss = valid ? s : 0;
            const float4* hp = reinterpret_cast<const float4*>(&sHid[ss * 36]);
            float ea = 0.0f, eb = 0.0f;
            #pragma unroll
            for (int hh = 0; hh < 8; ++hh) {
                float4 hv = hp[hh];
                ea += hv.x * w2c[4 * hh] + hv.y * w2c[4 * hh + 1];
                eb += hv.z * w2c[4 * hh + 2] + hv.w * w2c[4 * hh + 3];
            }
            float e = b2o + ea + eb;
            float delta = 0.0f;
            if (ss >= 1 && ss <= 8) delta = Lrow[ss - 1];
            else if (ss >= 9)       delta = -Lrow[ss - 9];
            float p = xreg + delta + e;
            pf[g] = p;
            if (valid && s >= 1) xsum += p;      // Wm[0] = 0
        }
        xsum += __shfl_xor_sync(FULLMASK, xsum, 8);
        xsum += __shfl_xor_sync(FULLMASK, xsum, 16);
        const float xpred = xsum * 0.0625f;
        if (lane < 8) sXp[o] = xpred;
        #pragma unroll
        for (int g = 0; g < 5; ++g) {
            int s = 4 * g + q;
            if (s < 17) sDxT[o * 20 + s] = pf[g] - xpred;
        }
        __syncwarp();

        // ==== Cx (16x scaled): a1=16*Cx[i1][o], a2=16*Cx[i2][o], dual accumulators ====
        float a1, a2;
        {
            const float4* cq = reinterpret_cast<const float4*>(&sDxT[i1 * 20]);
            const float4* c2 = reinterpret_cast<const float4*>(&sDxT[i2 * 20]);
            const float4* co = reinterpret_cast<const float4*>(&sDxT[o * 20]);
            float4 xq = cq[0], x2 = c2[0], xo = co[0];
            float a1a = 32.0f * xq.x * xo.x + xq.y * xo.y;   // Wc0 = 2 = 32/16
            float a1b = xq.z * xo.z + xq.w * xo.w;
            float a2a = 32.0f * x2.x * xo.x + x2.y * xo.y;
            float a2b = x2.z * xo.z + x2.w * xo.w;
            #pragma unroll
            for (int c = 1; c < 4; ++c) {
                xq = cq[c]; x2 = c2[c]; xo = co[c];
                a1a += xq.x * xo.x + xq.y * xo.y;
                a1b += xq.z * xo.z + xq.w * xo.w;
                a2a += x2.x * xo.x + x2.y * xo.y;
                a2b += x2.z * xo.z + x2.w * xo.w;
            }
            float q16 = sDxT[i1 * 20 + 16], t16 = sDxT[i2 * 20 + 16], o16 = sDxT[o * 20 + 16];
            a1 = a1a + a1b + q16 * o16;
            a2 = a2a + a2b + t16 * o16;
        }
        const float ppa = a1 * 0.0625f + cD1;   // P_pred[i1][o]
        const float ppb = a2 * 0.0625f + cD2;   // P_pred[i2][o]
        sPp[i1 * 8 + o] = ppa;
        sPp[i2 * 8 + o] = ppb;
        __syncwarp();

        // ==== Pxy[pn][m] = (P_pred - diag(Q+JIT)) row_pn . Hm row_m ====
        float pxy;
        {
            const float4* pr = reinterpret_cast<const float4*>(&sPp[pn * 8]);
            float4 p0 = pr[0], p1v = pr[1];
            float pa = p0.x * hmr[0] + p0.y * hmr[1] + p0.z * hmr[2];
            float pb = p0.w * hmr[3] + p1v.x * hmr[4] + p1v.y * hmr[5];
            float pc = p1v.z * hmr[6] + p1v.w * hmr[7] - corrP;
            pxy = pa + pb + pc;
        }
        // ==== Sy[si][m] = Hm row_si . Pxy col_m + R ====
        float syv;
        {
            float sa = radd, sb = 0.0f;
            #pragma unroll
            for (int d = 0; d < 8; d += 2) {
                sa += hsr[d] * __shfl_sync(FULLMASK, pxy, d * 4 + m);
                sb += hsr[d + 1] * __shfl_sync(FULLMASK, pxy, (d + 1) * 4 + m);
            }
            syv = sa + sb;
        }

        // ==== gather the 10 unique Sy entries to every lane ====
        const float Saa = __shfl_sync(FULLMASK, syv, 0);
        const float Sab = __shfl_sync(FULLMASK, syv, 1);
        const float Sac = __shfl_sync(FULLMASK, syv, 2);
        const float Sad = __shfl_sync(FULLMASK, syv, 3);
        const float Sbb = __shfl_sync(FULLMASK, syv, 5);
        const float Sbc = __shfl_sync(FULLMASK, syv, 6);
        const float Sbd = __shfl_sync(FULLMASK, syv, 7);
        const float Scc = __shfl_sync(FULLMASK, syv, 10);
        const float Scd = __shfl_sync(FULLMASK, syv, 11);
        const float Sdd = __shfl_sync(FULLMASK, syv, 15);

        // ==== closed-form symmetric 4x4 inverse (2x2-subdet scheme) ====
        const float s0 = Saa * Sbb - Sab * Sab;
        const float s1 = Saa * Sbc - Sab * Sac;
        const float s2 = Saa * Sbd - Sab * Sad;
        const float s3 = Sab * Sbc - Sbb * Sac;
        const float s4 = Sab * Sbd - Sbb * Sad;
        const float s5 = Sac * Sbd - Sbc * Sad;
        const float c5 = Scc * Sdd - Scd * Scd;
        const float c4 = Sbc * Sdd - Sbd * Scd;
        const float c3 = Sbc * Scd - Sbd * Scc;
        const float c2 = Sac * Sdd - Sad * Scd;
        const float c1 = Sac * Scd - Sad * Scc;
        const float c0 = s5;
        const float det = s0 * c5 - s1 * c4 + s2 * c3 + s3 * c2 - s4 * c1 + s5 * c0;
        const float rdet = __fdividef(1.0f, det);
        if (lane == 0) outR[(long)b * T + t] = 0.5f * __logf(det);
        const float A00 =  Sbb * c5 - Sbc * c4 + Sbd * c3;
        const float A01 = -Sab * c5 + Sac * c4 - Sad * c3;
        const float A02 =  Sbd * s5 - Scd * s4 + Sdd * s3;
        const float A03 = -Sbc * s5 + Scc * s4 - Scd * s3;
        const float A11 =  Saa * c5 - Sac * c2 + Sad * c1;
        const float A12 = -Sad * s5 + Scd * s2 - Sdd * s1;
        const float A13 =  Sac * s5 - Scc * s2 + Scd * s1;
        const float A22 =  Sad * s4 - Sbd * s2 + Sdd * s0;
        const float A23 = -Sac * s4 + Sbc * s2 - Scd * s0;
        const float A33 =  Sac * s3 - Sbc * s1 + Scc * s0;

        // ==== K row o = Pxy row o * Sinv ====
        const float w0 = __shfl_sync(FULLMASK, pxy, o * 4 + 0);
        const float w1 = __shfl_sync(FULLMASK, pxy, o * 4 + 1);
        const float w2 = __shfl_sync(FULLMASK, pxy, o * 4 + 2);
        const float w3 = __shfl_sync(FULLMASK, pxy, o * 4 + 3);
        const float z0 = (w0 * A00 + w1 * A01 + w2 * A02 + w3 * A03) * rdet;
        const float z1 = (w0 * A01 + w1 * A11 + w2 * A12 + w3 * A13) * rdet;
        const float z2 = (w0 * A02 + w1 * A12 + w2 * A22 + w3 * A23) * rdet;
        const float z3 = (w0 * A03 + w1 * A13 + w2 * A23 + w3 * A33) * rdet;

        // ==== innovation (from sXp) & state update ====
        float inno;
        {
            const float4* xp4 = reinterpret_cast<const float4*>(sXp);
            float4 x0 = xp4[0], x1 = xp4[1];
            float ya = hmr[0] * x0.x + hmr[1] * x0.y + hmr[2] * x0.z + hmr[3] * x0.w;
            float yb = hmr[4] * x1.x + hmr[5] * x1.y + hmr[6] * x1.z + hmr[7] * x1.w;
            inno = yraw - (ya + yb);
        }
        const float in0 = __shfl_sync(FULLMASK, inno, b4 + 0);
        const float in1 = __shfl_sync(FULLMASK, inno, b4 + 1);
        const float in2 = __shfl_sync(FULLMASK, inno, b4 + 2);
        const float in3 = __shfl_sync(FULLMASK, inno, b4 + 3);
        float xn = xpred + z0 * in0 + z1 * in1 + z2 * in2 + z3 * in3;
        xreg = xn;
        if (lane < 8) { sX[o] = xn; outX[((long)b * T + t) * 8 + o] = xn; }

        // ==== P_new = Ppred - K Pxy^T + JIT*I (symmetric to fp noise) ====
        const float Ka0 = __shfl_sync(FULLMASK, z0, q);
        const float Ka1 = __shfl_sync(FULLMASK, z1, q);
        const float Ka2 = __shfl_sync(FULLMASK, z2, q);
        const float Ka3 = __shfl_sync(FULLMASK, z3, q);
        const float Kb0 = __shfl_sync(FULLMASK, z0, q + 4);
        const float Kb1 = __shfl_sync(FULLMASK, z1, q + 4);
        const float Kb2 = __shfl_sync(FULLMASK, z2, q + 4);
        const float Kb3 = __shfl_sync(FULLMASK, z3, q + 4);
        float p1 = ppa - (Ka0 * w0 + Ka1 * w1 + Ka2 * w2 + Ka3 * w3) + ((i1 == o) ? JIT : 0.0f);
        float p2 = ppb - (Kb0 * w0 + Kb1 * w1 + Kb2 * w2 + Kb3 * w3) + ((i2 == o) ? JIT : 0.0f);
        sP[i1 * 8 + o] = p1;
        sP[i2 * 8 + o] = p2;
        long bp = ((long)b * T + t) * 64;
        outP[bp + i1 * 8 + o] = p1;
        outP[bp + i2 * 8 + o] = p2;
        __syncwarp();
    }

    // ==== epilogue: q_e[T-1] from final P_pred (scalar root-free pivots) ====
    {
        float a[8];
        #pragma unroll
        for (int c = 0; c < 8; ++c) a[c] = sPp[o * 8 + c];
        float myd = 1.0f;
        #pragma unroll
        for (int k = 0; k < 8; ++k) {
            float dk = __shfl_sync(FULLMASK, a[k], k);
            float isq = rsqrtf(dk);
            float rc = isq * isq;
            myd = (o == k) ? dk : myd;
            float tt = a[k] * rc;
            #pragma unroll
            for (int jj = k + 1; jj < 8; ++jj) {
                float lj = __shfl_sync(FULLMASK, a[k], jj);
                a[jj] -= tt * lj;
            }
        }
        float lg = __logf(myd);
        lg += __shfl_xor_sync(FULLMASK, lg, 1);
        lg += __shfl_xor_sync(FULLMASK, lg, 2);
        lg += __shfl_xor_sync(FULLMASK, lg, 4);
        if (lane == 0) outQ[(long)b * T + (T - 1)] = 0.5f * lg;
    }
}

extern "C" void kernel_launch(void* const* d_in, const int* in_sizes, int n_in,
                              void* d_out, int out_size) {
    const float* X0  = (const float*)d_in[0];
    const float* u   = (const float*)d_in[1];
    const float* yv  = (const float*)d_in[2];
    const float* W1  = (const float*)d_in[3];
    const float* b1  = (const float*)d_in[4];
    const float* W2  = (const float*)d_in[5];
    const float* b2  = (const float*)d_in[6];
    const float* Hm  = (const float*)d_in[7];
    const float* lq  = (const float*)d_in[8];
    const float* lr  = (const float*)d_in[9];
    const float* lp0 = (const float*)d_in[10];

    const int B = in_sizes[0] / 8;                 // 1024
    const int T = in_sizes[1] / (B * 2);           // 256

    float* out  = (float*)d_out;
    float* outX = out;
    float* outP = out + (long)B * T * 8;
    float* outQ = out + (long)B * T * (8 + 64);
    float* outR = outQ + (long)B * T;

    ukf_kernel<<<B, 32>>>(X0, u, yv, W1, b1, W2, b2, Hm, lq, lr, lp0,
                          outX, outP, outQ, outR, T);
}